// round 15
// baseline (speedup 1.0000x reference)
#include <cuda_runtime.h>
#include <cuda_bf16.h>
#include <math.h>

#define N_TAGS 48
#define ROOT 46
#define END_TAG 47
#define BATCH 512
#define MAXT 256
#define WARPS 8         // 8 sequences per CTA -> 2 warps per SMSP, grid 64

typedef unsigned long long ull;

// dynamic smem layout:
//   F16 : __nv_bfloat16[WARPS][MAXT][N_TAGS]   (192 KB)
//   se  : float[WARPS][2][N_TAGS]              (3 KB, 16B aligned)
#define FEATS_ELEMS (WARPS * MAXT * N_TAGS)
#define SE_OFF      (FEATS_ELEMS * 2)
#define SMEM_BYTES  (SE_OFF + WARPS * 2 * N_TAGS * 4)

__device__ __forceinline__ ull fma2(ull a, ull b, ull c) {
    ull d;
    asm("fma.rn.f32x2 %0, %1, %2, %3;" : "=l"(d) : "l"(a), "l"(b), "l"(c));
    return d;
}
__device__ __forceinline__ ull add2(ull a, ull b) {
    ull d;
    asm("add.rn.f32x2 %0, %1, %2;" : "=l"(d) : "l"(a), "l"(b));
    return d;
}
__device__ __forceinline__ ull pack2(float lo, float hi) {
    ull d;
    asm("mov.b64 %0, {%1, %2};" : "=l"(d) : "f"(lo), "f"(hi));
    return d;
}
__device__ __forceinline__ float sum2(ull a) {
    float lo, hi;
    asm("mov.b64 {%0, %1}, %2;" : "=f"(lo), "=f"(hi) : "l"(a));
    return lo + hi;
}
__device__ __forceinline__ float frcp(float x) {
    float y;
    asm("rcp.approx.f32 %0, %1;" : "=f"(y) : "f"(x));
    return y;
}

__global__ __launch_bounds__(32 * WARPS)
void crf_nll_kernel(const float* __restrict__ feats,
                    const int* __restrict__ tags,
                    const int* __restrict__ lengths,
                    const float* __restrict__ lt,
                    float* __restrict__ out)
{
    extern __shared__ __align__(16) char smem_raw[];
    __nv_bfloat16* F16all = (__nv_bfloat16*)smem_raw;
    float (*se)[2][N_TAGS] = (float (*)[2][N_TAGS])(smem_raw + SE_OFF);

    const int w = threadIdx.x >> 5;         // warp -> SMSP w%4
    const int j = threadIdx.x & 31;
    const int jb = 32 + (j & 15);           // b-column tag
    const int b = blockIdx.x * WARPS + w;   // one batch per warp
    const bool hasB = (j < 16);

    const int len = lengths[b];
    const long fbase = (long)b * MAXT * N_TAGS;   // global fp32 feats base
    const int tbase = b * MAXT;

    // ---------------- stage ALL 8 sequences' feats into smem as bf16 -------
    {
        const float4* src4 = (const float4*)(feats + (long)blockIdx.x * FEATS_ELEMS);
        uint2* dst = (uint2*)F16all;
        #pragma unroll 4
        for (int i = threadIdx.x; i < FEATS_ELEMS / 4; i += 32 * WARPS) {
            float4 v = src4[i];
            __nv_bfloat162 lo = __float22bfloat162_rn(make_float2(v.x, v.y));
            __nv_bfloat162 hi = __float22bfloat162_rn(make_float2(v.z, v.w));
            uint2 pkt;
            pkt.x = *(unsigned int*)&lo;
            pkt.y = *(unsigned int*)&hi;
            dst[i] = pkt;
        }
    }

    // ---------------- gold score + Σf0_bf16 (global fp32; overlaps staging) -
    float gold, sumf0;
    {
        float g = 0.0f, s0 = 0.0f;
        for (int t = j; t < MAXT; t += 32) {
            if (t < len) {
                int tg = tags[tbase + t];
                g += feats[fbase + t * N_TAGS + tg];
                if (t >= 1) {
                    int tp = tags[tbase + t - 1];
                    g += lt[tp * N_TAGS + tg];
                    // f0 ledger uses the SAME bf16 value as the loop normalizer
                    s0 += __bfloat162float(__float2bfloat16_rn(feats[fbase + t * N_TAGS]));
                }
            }
        }
        if (j == 0) {
            int t0 = tags[tbase];
            int tl = tags[tbase + len - 1];
            g += lt[ROOT * N_TAGS + t0] + lt[tl * N_TAGS + END_TAG];
        }
        #pragma unroll
        for (int off = 16; off; off >>= 1) {
            g  += __shfl_xor_sync(0xffffffffu, g, off);
            s0 += __shfl_xor_sync(0xffffffffu, s0, off);
        }
        gold = g;
        sumf0 = s0;
    }

    // ---------------- packed E columns in registers -------------------------
    ull EPa[N_TAGS / 2], EPb[N_TAGS / 2];
    #pragma unroll
    for (int k = 0; k < N_TAGS / 2; k++) {
        float lo = __expf(lt[(2 * k) * N_TAGS + j]);
        float hi = __expf(lt[(2 * k + 1) * N_TAGS + j]);
        EPa[k] = pack2(lo, hi);
        float lob = hasB ? __expf(lt[(2 * k) * N_TAGS + jb]) : 0.0f;
        float hib = hasB ? __expf(lt[(2 * k + 1) * N_TAGS + jb]) : 0.0f;
        EPb[k] = pack2(lob, hib);
    }

    const float lt_end_a = lt[j * N_TAGS + END_TAG];
    const float lt_end_b = hasB ? lt[jb * N_TAGS + END_TAG] : 0.0f;

    // ---------------- init from fp32 global (t=0 exact) ---------------------
    float S = lt[ROOT * N_TAGS + 0] + feats[fbase + 0];
    float r_a = __expf(lt[ROOT * N_TAGS + j] + feats[fbase + j] - S);
    float r_b = hasB ? __expf(lt[ROOT * N_TAGS + jb] + feats[fbase + jb] - S) : 0.0f;

    __syncthreads();   // staged bf16 feats visible to all warps

    const __nv_bfloat16* F = F16all + w * MAXT * N_TAGS;

    // lookahead: exp of bf16 f(t=1)
    float efa = __expf(__bfloat162float(F[N_TAGS + j]));
    float efb = __expf(__bfloat162float(F[N_TAGS + jb]));

    // publish r(0)
    se[w][0][j] = r_a;
    if (hasB) se[w][0][32 + j] = r_b;
    __syncwarp();

    // ---------------- forward recurrence: all-smem, log-free path ----------
    float Lacc = 0.0f;    // Σ log(r0prev)
    int cur = 0;
    for (int t = 1; t < len; ++t) {
        float ea = efa, eb = efb;                // exp(f_bf(t)), ready

        // lookahead t+1 (off the recurrence path)
        int tn = (t + 1 < MAXT) ? (t + 1) : 0;
        efa = __expf(__bfloat162float(F[tn * N_TAGS + j]));
        efb = __expf(__bfloat162float(F[tn * N_TAGS + jb]));

        // normalizer chain hides under the dot
        float e0 = __shfl_sync(0xffffffffu, ea, 0);   // exp(f_bf(t,0))
        float r0prev = se[w][cur][0];                 // broadcast LDS
        float inv = frcp(r0prev * e0);
        float ka = ea * inv;
        float kb = eb * inv;

        Lacc += __logf(r0prev);                       // off-path side chain

        // packed dot: 48 fma.rn.f32x2 covering both output columns
        const ulonglong2* se2 = (const ulonglong2*)se[w][cur];
        ull a0 = 0, a1 = 0, a2 = 0, a3 = 0;
        ull b0 = 0, b1 = 0, b2 = 0, b3 = 0;
        #pragma unroll
        for (int i = 0; i < 12; i += 2) {
            ulonglong2 w0 = se2[i];
            ulonglong2 w1 = se2[i + 1];
            a0 = fma2(w0.x, EPa[2 * i + 0], a0);
            a1 = fma2(w0.y, EPa[2 * i + 1], a1);
            a2 = fma2(w1.x, EPa[2 * i + 2], a2);
            a3 = fma2(w1.y, EPa[2 * i + 3], a3);
            b0 = fma2(w0.x, EPb[2 * i + 0], b0);
            b1 = fma2(w0.y, EPb[2 * i + 1], b1);
            b2 = fma2(w1.x, EPb[2 * i + 2], b2);
            b3 = fma2(w1.y, EPb[2 * i + 3], b3);
        }
        float sa = sum2(add2(add2(a0, a1), add2(a2, a3)));
        float sb = sum2(add2(add2(b0, b1), add2(b2, b3)));

        r_a = sa * ka;
        r_b = sb * kb;

        se[w][cur ^ 1][j] = r_a;
        if (hasB) se[w][cur ^ 1][32 + j] = r_b;
        __syncwarp();
        cur ^= 1;
    }

    // S_total = S0 + Σ log(r0prev) + Σ f0_bf16  (consistent with normalizer)
    S += Lacc + sumf0;

    // ---------------- partition = lse over 48 terminal scores ----------------
    float pa = S + __logf(r_a) + lt_end_a;
    float pb = hasB ? (S + __logf(r_b) + lt_end_b) : -INFINITY;
    float m = fmaxf(pa, pb);
    #pragma unroll
    for (int off = 16; off; off >>= 1)
        m = fmaxf(m, __shfl_xor_sync(0xffffffffu, m, off));

    float ex = __expf(pa - m) + (hasB ? __expf(pb - m) : 0.0f);
    #pragma unroll
    for (int off = 16; off; off >>= 1)
        ex += __shfl_xor_sync(0xffffffffu, ex, off);

    if (j == 0)
        out[b] = m + __logf(ex) - gold;
}

extern "C" void kernel_launch(void* const* d_in, const int* in_sizes, int n_in,
                              void* d_out, int out_size)
{
    const float* feats = nullptr;
    const int*   tags = nullptr;
    const int*   lengths = nullptr;
    const float* lt = nullptr;

    for (int i = 0; i < n_in; i++) {
        switch (in_sizes[i]) {
            case BATCH * MAXT * N_TAGS: feats   = (const float*)d_in[i]; break;
            case BATCH * MAXT:          tags    = (const int*)d_in[i];   break;
            case BATCH:                 lengths = (const int*)d_in[i];   break;
            case N_TAGS * N_TAGS:       lt      = (const float*)d_in[i]; break;
        }
    }

    static bool attr_set = false;   // attribute config, not a guard on work
    if (!attr_set) {
        cudaFuncSetAttribute(crf_nll_kernel,
                             cudaFuncAttributeMaxDynamicSharedMemorySize,
                             SMEM_BYTES);
        attr_set = true;
    }

    crf_nll_kernel<<<BATCH / WARPS, 32 * WARPS, SMEM_BYTES>>>(
        feats, tags, lengths, lt, (float*)d_out);
}